// round 11
// baseline (speedup 1.0000x reference)
#include <cuda_runtime.h>

#define NSEG 256
#define DDIM 256
#define TPB  256
#define MAXN 4096   // key scratch capacity (N=2048 here)
#define SPLIT 4     // chunks per protein — best measured accumulate (R8)

// Written by pre-kernel block 0 each call (no zero-init needed — overwritten).
__device__ int   g_keys[MAXN];    // keys converted to int32
__device__ float g_scale[NSEG];   // 1 / (count_b * L)

// ---------------------------------------------------------------------------
// Kernel A: zero d_out (poisoned by harness); block 0 additionally converts
// keys and builds the per-segment scale table.
//
// Key dtype detect: viewing the buffer as int32 words, int64 values < 256
// have all-zero odd words within the first nkeys words, while sorted int32
// keys reach nonzero values at odd indices.
__global__ void __launch_bounds__(TPB) pp_pre_kernel(
    const int* __restrict__ kwords,    // keys viewed as int32 words
    float4* __restrict__ out4,         // d_out as float4
    int nout4, int nkeys, float Lf)
{
    int i = blockIdx.x * blockDim.x + threadIdx.x;
    if (i < nout4) out4[i] = make_float4(0.f, 0.f, 0.f, 0.f);

    if (blockIdx.x == 0) {
        const int tid = threadIdx.x;
        __shared__ int hist[NSEG];
        hist[tid] = 0;

        // dtype detect
        int local = 0;
        for (int k = tid; k < nkeys; k += TPB)
            if ((k & 1) && kwords[k] != 0) local = 1;
        const int is32 = __syncthreads_or(local);

        // convert keys + histogram counts (smem atomics)
        for (int n = tid; n < nkeys; n += TPB) {
            int key = is32 ? kwords[n] : kwords[2 * n];   // int64 lo word
            key &= (NSEG - 1);                            // never OOB
            g_keys[n] = key;
            atomicAdd(&hist[key], 1);
        }
        __syncthreads();

        int c = hist[tid];
        g_scale[tid] = __fdividef(1.0f, (float)(c > 0 ? c : 1) * Lf);
    }
}

// ---------------------------------------------------------------------------
// Kernel B: one block per protein CHUNK (SPLIT=4 chunks per protein; best
// measured DRAM-active: small T_CTA shrinks wave-quantization + drain).
// Launched with PDL: starts while pp_pre_kernel is in flight. The streaming
// loop is independent of the pre-kernel; cudaGridDependencySynchronize()
// sits AFTER the stream so the pre-kernel's ~2us + launch gap hide fully
// (verified in R9: e2e == accumulate duration).
//
// Each thread strides float4s of its 1/SPLIT slice (coalesced 128B
// transactions); stride 256 over 64 float4s/row keeps each thread in column
// group (tid % 64). Cross-thread fold in smem, then threads 0..63 atomicAdd
// pre-scaled partials into d_out (2M REDGs over 64K addresses).
__global__ void __launch_bounds__(TPB) pp_accum_kernel(
    const float4* __restrict__ in,       // [N, L*D/4]
    float* __restrict__ out,             // [NSEG, DDIM]
    int vec_per_protein)                 // L*D/4
{
    __shared__ float4 sm[TPB];
    const int chunk = blockIdx.x;
    const int n     = chunk / SPLIT;       // protein
    const int c     = chunk % SPLIT;       // chunk within protein
    const int tid   = threadIdx.x;
    const int vec_per_chunk = vec_per_protein / SPLIT;

    const float4* base = in + (size_t)n * (size_t)vec_per_protein
                            + (size_t)c * (size_t)vec_per_chunk;
    float4 acc = make_float4(0.f, 0.f, 0.f, 0.f);
    #pragma unroll 4
    for (int idx = tid; idx < vec_per_chunk; idx += TPB) {
        float4 v = base[idx];
        acc.x += v.x; acc.y += v.y; acc.z += v.z; acc.w += v.w;
    }
    sm[tid] = acc;

    // Wait for pp_pre_kernel completion (PDL) before touching its outputs.
    cudaGridDependencySynchronize();
    __syncthreads();

    const int   b     = g_keys[n];
    const float scale = g_scale[b];

    if (tid < 64) {
        float4 a0 = sm[tid];
        float4 a1 = sm[tid + 64];
        float4 a2 = sm[tid + 128];
        float4 a3 = sm[tid + 192];
        float* dst = out + b * DDIM + tid * 4;
        atomicAdd(dst + 0, (a0.x + a1.x + a2.x + a3.x) * scale);
        atomicAdd(dst + 1, (a0.y + a1.y + a2.y + a3.y) * scale);
        atomicAdd(dst + 2, (a0.z + a1.z + a2.z + a3.z) * scale);
        atomicAdd(dst + 3, (a0.w + a1.w + a2.w + a3.w) * scale);
    }
}

// ---------------------------------------------------------------------------
extern "C" void kernel_launch(void* const* d_in, const int* in_sizes, int n_in,
                              void* d_out, int out_size) {
    // Pick embeds by element count (defend against input-order surprises).
    int ei = 0, ki = 1;
    if (n_in >= 2 && in_sizes[1] > in_sizes[0]) { ei = 1; ki = 0; }

    const float* embeds = (const float*)d_in[ei];   // [N, L, D] fp32
    const int*   kwords = (const int*)d_in[ki];     // [N] int32 or int64 (words)

    const int N            = in_sizes[ki];
    const int per_protein  = in_sizes[ei] / N;      // L * D
    const int L            = per_protein / DDIM;    // sequence length
    const int vec_per_prot = per_protein / 4;
    const int nout4        = out_size / 4;

    pp_pre_kernel<<<(nout4 + TPB - 1) / TPB, TPB>>>(
        kwords, (float4*)d_out, nout4, N, (float)L);

    // Accumulate with programmatic dependent launch: overlaps the pre-kernel.
    cudaLaunchConfig_t cfg = {};
    cfg.gridDim  = dim3((unsigned)(N * SPLIT), 1, 1);
    cfg.blockDim = dim3(TPB, 1, 1);
    cudaLaunchAttribute attrs[1];
    attrs[0].id = cudaLaunchAttributeProgrammaticStreamSerialization;
    attrs[0].val.programmaticStreamSerializationAllowed = 1;
    cfg.attrs    = attrs;
    cfg.numAttrs = 1;
    cudaLaunchKernelEx(&cfg, pp_accum_kernel,
                       (const float4*)embeds, (float*)d_out, vec_per_prot);
}

// round 14
// speedup vs baseline: 1.0208x; 1.0208x over previous
#include <cuda_runtime.h>

#define NSEG 256
#define DDIM 256
#define TPB  256
#define MAXN 4096   // key scratch capacity (N=2048 here)
#define SPLIT 2     // chunks per protein: middle of measured SPLIT=1/4 tradeoff

// Written by pre-kernel block 0 each call (no zero-init needed — overwritten).
__device__ int   g_keys[MAXN];    // keys converted to int32
__device__ float g_scale[NSEG];   // 1 / (count_b * L)

// ---------------------------------------------------------------------------
// Kernel A: zero d_out (poisoned by harness); block 0 additionally converts
// keys and builds the per-segment scale table.
//
// Key dtype detect: viewing the buffer as int32 words, int64 values < 256
// have all-zero odd words within the first nkeys words, while sorted int32
// keys reach nonzero values at odd indices.
__global__ void __launch_bounds__(TPB) pp_pre_kernel(
    const int* __restrict__ kwords,    // keys viewed as int32 words
    float4* __restrict__ out4,         // d_out as float4
    int nout4, int nkeys, float Lf)
{
    int i = blockIdx.x * blockDim.x + threadIdx.x;
    if (i < nout4) out4[i] = make_float4(0.f, 0.f, 0.f, 0.f);

    if (blockIdx.x == 0) {
        const int tid = threadIdx.x;
        __shared__ int hist[NSEG];
        hist[tid] = 0;

        // dtype detect
        int local = 0;
        for (int k = tid; k < nkeys; k += TPB)
            if ((k & 1) && kwords[k] != 0) local = 1;
        const int is32 = __syncthreads_or(local);

        // convert keys + histogram counts (smem atomics)
        for (int n = tid; n < nkeys; n += TPB) {
            int key = is32 ? kwords[n] : kwords[2 * n];   // int64 lo word
            key &= (NSEG - 1);                            // never OOB
            g_keys[n] = key;
            atomicAdd(&hist[key], 1);
        }
        __syncthreads();

        int c = hist[tid];
        g_scale[tid] = __fdividef(1.0f, (float)(c > 0 ? c : 1) * Lf);
    }
}

// ---------------------------------------------------------------------------
// Kernel B: one block per protein CHUNK (SPLIT=2). Launched with PDL: starts
// while pp_pre_kernel is in flight; cudaGridDependencySynchronize() sits
// AFTER the independent streaming loop, so the pre-kernel's ~2us + launch gap
// hide fully (verified R9: e2e == accum duration at SPLIT=1).
//
// grid = 2*N keeps off-kernel launch/wave cost near the SPLIT=1 level (the
// e2e-vs-profiled comparison across R6/R8/R11 showed grid=8192 paying ~5-6us
// outside the kernel clock) while halving T_CTA to shrink the tail drain.
//
// Each thread strides float4s of its half-protein slice (coalesced 128B
// transactions); stride 256 over 64 float4s/row keeps each thread in column
// group (tid % 64). Cross-thread fold in smem, then threads 0..63 atomicAdd
// pre-scaled partials into d_out (1M REDGs over 64K addresses).
__global__ void __launch_bounds__(TPB) pp_accum_kernel(
    const float4* __restrict__ in,       // [N, L*D/4]
    float* __restrict__ out,             // [NSEG, DDIM]
    int vec_per_protein)                 // L*D/4
{
    __shared__ float4 sm[TPB];
    const int chunk = blockIdx.x;
    const int n     = chunk / SPLIT;       // protein
    const int c     = chunk % SPLIT;       // chunk within protein
    const int tid   = threadIdx.x;
    const int vec_per_chunk = vec_per_protein / SPLIT;

    const float4* base = in + (size_t)n * (size_t)vec_per_protein
                            + (size_t)c * (size_t)vec_per_chunk;
    float4 acc = make_float4(0.f, 0.f, 0.f, 0.f);
    #pragma unroll 4
    for (int idx = tid; idx < vec_per_chunk; idx += TPB) {
        float4 v = base[idx];
        acc.x += v.x; acc.y += v.y; acc.z += v.z; acc.w += v.w;
    }
    sm[tid] = acc;

    // Wait for pp_pre_kernel completion (PDL) before touching its outputs.
    cudaGridDependencySynchronize();
    __syncthreads();

    const int   b     = g_keys[n];
    const float scale = g_scale[b];

    if (tid < 64) {
        float4 a0 = sm[tid];
        float4 a1 = sm[tid + 64];
        float4 a2 = sm[tid + 128];
        float4 a3 = sm[tid + 192];
        float* dst = out + b * DDIM + tid * 4;
        atomicAdd(dst + 0, (a0.x + a1.x + a2.x + a3.x) * scale);
        atomicAdd(dst + 1, (a0.y + a1.y + a2.y + a3.y) * scale);
        atomicAdd(dst + 2, (a0.z + a1.z + a2.z + a3.z) * scale);
        atomicAdd(dst + 3, (a0.w + a1.w + a2.w + a3.w) * scale);
    }
}

// ---------------------------------------------------------------------------
extern "C" void kernel_launch(void* const* d_in, const int* in_sizes, int n_in,
                              void* d_out, int out_size) {
    // Pick embeds by element count (defend against input-order surprises).
    int ei = 0, ki = 1;
    if (n_in >= 2 && in_sizes[1] > in_sizes[0]) { ei = 1; ki = 0; }

    const float* embeds = (const float*)d_in[ei];   // [N, L, D] fp32
    const int*   kwords = (const int*)d_in[ki];     // [N] int32 or int64 (words)

    const int N            = in_sizes[ki];
    const int per_protein  = in_sizes[ei] / N;      // L * D
    const int L            = per_protein / DDIM;    // sequence length
    const int vec_per_prot = per_protein / 4;
    const int nout4        = out_size / 4;

    pp_pre_kernel<<<(nout4 + TPB - 1) / TPB, TPB>>>(
        kwords, (float4*)d_out, nout4, N, (float)L);

    // Accumulate with programmatic dependent launch: overlaps the pre-kernel.
    cudaLaunchConfig_t cfg = {};
    cfg.gridDim  = dim3((unsigned)(N * SPLIT), 1, 1);
    cfg.blockDim = dim3(TPB, 1, 1);
    cudaLaunchAttribute attrs[1];
    attrs[0].id = cudaLaunchAttributeProgrammaticStreamSerialization;
    attrs[0].val.programmaticStreamSerializationAllowed = 1;
    cfg.attrs    = attrs;
    cfg.numAttrs = 1;
    cudaLaunchKernelEx(&cfg, pp_accum_kernel,
                       (const float4*)embeds, (float*)d_out, vec_per_prot);
}